// round 2
// baseline (speedup 1.0000x reference)
#include <cuda_runtime.h>
#include <cuda_bf16.h>

#define L1N 16          // L2+1
#define DIN 1536
#define COUNT 8
#define L3N 64
#define BMAX 16384
#define CTA_SAMPLES 128
#define CK 32           // k-chunk
#define NCHUNK (DIN / CK)
#define XST 36          // x smem row stride (floats): conflict-free for fp32x4 r/w
#define HB 64           // max histogram blocks

// ---- device scratch ----
__device__ float g_wsum[COUNT * DIN * L1N];   // [b][k][o], o contiguous
__device__ float g_bsum[COUNT * L1N];
__device__ float g_w2p[COUNT * L3N * 32];     // W2 padded 30 -> 32
__device__ int   g_bh[HB * COUNT];            // per-block bucket counts
__device__ int   g_boff[HB * COUNT];          // per-block bucket write offsets
__device__ int   g_aoff[COUNT + 1];
__device__ int   g_order[BMAX + COUNT * CTA_SAMPLES];

// ---------------- prep: fold W1+Wf, pad W2, zero per-block hist ----------------
__global__ void k_prep(const float* __restrict__ W1, const float* __restrict__ b1,
                       const float* __restrict__ Wf, const float* __restrict__ bf,
                       const float* __restrict__ W2) {
    int tid = blockIdx.x * blockDim.x + threadIdx.x;
    int stride = gridDim.x * blockDim.x;
    for (int idx = tid; idx < COUNT * DIN * L1N; idx += stride) {
        int b = idx / (DIN * L1N);
        int r = idx - b * (DIN * L1N);
        int k = r >> 4;
        int o = r & 15;
        g_wsum[idx] = W1[(b * L1N + o) * DIN + k] + Wf[o * DIN + k];
    }
    for (int idx = tid; idx < COUNT * L3N * 32; idx += stride) {
        int b = idx >> 11;
        int j = (idx >> 5) & 63;
        int i = idx & 31;
        g_w2p[idx] = (i < 30) ? W2[(b * L3N + j) * 30 + i] : 0.0f;
    }
    for (int idx = tid; idx < COUNT * L1N; idx += stride) {
        int b = idx >> 4, o = idx & 15;
        g_bsum[idx] = b1[b * L1N + o] + bf[o];
    }
    for (int idx = tid; idx < HB * COUNT; idx += stride) g_bh[idx] = 0;
}

// ---------------- per-block histogram (warp-aggregated, no global atomics) ----------------
__global__ void k_hist(const int* __restrict__ ls, int n) {
    __shared__ int sh[COUNT];
    int t = threadIdx.x;
    if (t < COUNT) sh[t] = 0;
    __syncthreads();
    int i = blockIdx.x * blockDim.x + t;
    if (i < n) {
        int b = ls[i];
        unsigned act = __activemask();
        unsigned m = __match_any_sync(act, b);
        int lane = t & 31;
        int leader = __ffs(m) - 1;
        if (lane == leader) atomicAdd(&sh[b], __popc(m));
    }
    __syncthreads();
    if (t < COUNT) g_bh[blockIdx.x * COUNT + t] = sh[t];
}

// ---------------- scan: bucket offsets (padded to 128), per-block offsets, sentinels ----------------
__global__ void k_scan() {
    __shared__ int sh[HB * COUNT];
    __shared__ int s_aoff[COUNT + 1];
    __shared__ int s_cnt[COUNT];
    int t = threadIdx.x;
    for (int i = t; i < HB * COUNT; i += blockDim.x) sh[i] = g_bh[i];
    __syncthreads();
    if (t < COUNT) {
        int tot = 0;
        for (int j = 0; j < HB; ++j) tot += sh[j * COUNT + t];
        s_cnt[t] = tot;
    }
    __syncthreads();
    if (t == 0) {
        int off = 0;
        for (int b = 0; b < COUNT; ++b) {
            s_aoff[b] = off;
            off += (s_cnt[b] + CTA_SAMPLES - 1) & ~(CTA_SAMPLES - 1);
        }
        s_aoff[COUNT] = off;
        for (int b = 0; b <= COUNT; ++b) g_aoff[b] = s_aoff[b];
    }
    __syncthreads();
    if (t < COUNT) {
        int run = s_aoff[t];
        for (int j = 0; j < HB; ++j) {
            g_boff[j * COUNT + t] = run;
            run += sh[j * COUNT + t];
        }
    }
    __syncthreads();
    for (int b = 0; b < COUNT; ++b) {
        int s = s_aoff[b] + s_cnt[b];
        int e = s_aoff[b + 1];
        for (int i = s + t; i < e; i += blockDim.x) g_order[i] = -1;
    }
}

// ---------------- scatter (smem-aggregated atomics only) ----------------
__global__ void k_scatter(const int* __restrict__ ls, int n) {
    __shared__ int cur[COUNT];
    int t = threadIdx.x;
    if (t < COUNT) cur[t] = g_boff[blockIdx.x * COUNT + t];
    __syncthreads();
    int i = blockIdx.x * blockDim.x + t;
    if (i < n) {
        int b = ls[i];
        unsigned act = __activemask();
        unsigned m = __match_any_sync(act, b);
        int lane = t & 31;
        int leader = __ffs(m) - 1;
        int rank = __popc(m & ((1u << lane) - 1u));
        int base = 0;
        if (lane == leader) base = atomicAdd(&cur[b], __popc(m));
        base = __shfl_sync(act, base, leader);
        g_order[base + rank] = i;
    }
}

// ---------------- main fused kernel ----------------
// smem floats: ws 24576 + w2p 2048 + bs 16 + b2 64 + wo 64 + x 2*128*36 + sidx 128(int)
#define SMEM_WORDS (24576 + 2048 + 16 + 64 + 64 + 2 * 128 * XST + 128)
#define SMEM_BYTES (SMEM_WORDS * 4)

__global__ void __launch_bounds__(128, 1) k_main(const float* __restrict__ x,
                                                 const float* __restrict__ b2,
                                                 const float* __restrict__ Wo,
                                                 const float* __restrict__ bo,
                                                 float* __restrict__ out) {
    extern __shared__ float sm[];
    float* ws   = sm;                  // [k][16]
    float* w2s  = ws + 24576;          // [j][32]
    float* bs   = w2s + 2048;          // 16
    float* b2s  = bs + 16;             // 64
    float* wos  = b2s + 64;            // 64
    float* xs0  = wos + 64;            // 128 * XST
    float* xs1  = xs0 + 128 * XST;     // 128 * XST
    int*  sidx_s = (int*)(xs1 + 128 * XST);  // 128

    int tid = threadIdx.x;
    int base = blockIdx.x * CTA_SAMPLES;
    if (base >= g_aoff[COUNT]) return;

    int b = 0;
#pragma unroll
    for (int t = 1; t < COUNT; ++t)
        if (base >= g_aoff[t]) b = t;

    // stage weights (coalesced from prepped gmem)
    {
        const float4* src = (const float4*)(g_wsum + b * (DIN * L1N));
        float4* dst = (float4*)ws;
        for (int i = tid; i < (DIN * L1N) / 4; i += 128) dst[i] = src[i];
    }
    {
        const float4* src = (const float4*)(g_w2p + b * (L3N * 32));
        float4* dst = (float4*)w2s;
        for (int i = tid; i < (L3N * 32) / 4; i += 128) dst[i] = src[i];
    }
    if (tid < 16) bs[tid] = g_bsum[b * L1N + tid];
    if (tid < 64) b2s[tid] = b2[b * L3N + tid];
    else if (tid < 128) wos[tid - 64] = Wo[b * L3N + (tid - 64)];
    {
        int v = g_order[base + tid];
        sidx_s[tid] = (v >= 0) ? v : 0;
    }
    int my_sidx = 0;  // own-lane sample (set after sync)
    __syncthreads();

    int own = g_order[base + tid];
    bool valid = own >= 0;
    my_sidx = valid ? own : 0;

    // ---- per-thread fixed loader assignment ----
    // thread loads float4 #(tid&7) of chunk rows for samples j*16 + (tid>>3), j=0..7
    int a = tid & 7;
    int srel = tid >> 3;
    const float4* rp[8];
#pragma unroll
    for (int j = 0; j < 8; ++j) {
        int s = j * 16 + srel;
        rp[j] = (const float4*)(x + (size_t)sidx_s[s] * DIN) + a;
    }

    // accumulators: 16 fp32 as 8 packed f32x2
    unsigned long long acc[8];
#pragma unroll
    for (int i = 0; i < 8; ++i) acc[i] = 0ULL;

    const ulonglong2* wp = (const ulonglong2*)ws;

    // prologue: load chunk 0
    float4 rb[8];
#pragma unroll
    for (int j = 0; j < 8; ++j) { rb[j] = rp[j][0]; rp[j] += CK / 4; }

#pragma unroll 1
    for (int c = 0; c < NCHUNK; ++c) {
        float* xb = (c & 1) ? xs1 : xs0;
        // STS chunk c (transpose): x_s[sample][k], conflict-free
#pragma unroll
        for (int j = 0; j < 8; ++j) {
            int s = j * 16 + srel;
            *(float4*)(xb + s * XST + a * 4) = rb[j];
        }
        __syncthreads();
        // prefetch chunk c+1
        if (c + 1 < NCHUNK) {
#pragma unroll
            for (int j = 0; j < 8; ++j) { rb[j] = rp[j][0]; rp[j] += CK / 4; }
        }
        // compute 32 k from this buffer
        const float* xrow = xb + tid * XST;
        int kg0 = c * CK;
#pragma unroll
        for (int kq = 0; kq < CK; kq += 4) {
            float4 xv = *(const float4*)(xrow + kq);
#pragma unroll
            for (int t4 = 0; t4 < 4; ++t4) {
                float xval = (t4 == 0) ? xv.x : (t4 == 1) ? xv.y : (t4 == 2) ? xv.z : xv.w;
                unsigned long long xd;
                asm("mov.b64 %0, {%1, %1};" : "=l"(xd) : "f"(xval));
                const ulonglong2* wr = wp + (unsigned)(kg0 + kq + t4) * 4;
#pragma unroll
                for (int p = 0; p < 4; ++p) {
                    ulonglong2 wv = wr[p];
                    asm("fma.rn.f32x2 %0, %1, %2, %0;"
                        : "+l"(acc[2 * p]) : "l"(xd), "l"(wv.x));
                    asm("fma.rn.f32x2 %0, %1, %2, %0;"
                        : "+l"(acc[2 * p + 1]) : "l"(xd), "l"(wv.y));
                }
            }
        }
    }

    float l1[16];
#pragma unroll
    for (int p = 0; p < 8; ++p) {
        float lo, hi;
        asm("mov.b64 {%0, %1}, %2;" : "=f"(lo), "=f"(hi) : "l"(acc[p]));
        l1[2 * p]     = lo + bs[2 * p];
        l1[2 * p + 1] = hi + bs[2 * p + 1];
    }

    // ---- layer 1 nonlinearity ----
    const float C = 127.0f / 128.0f;
    float lx[32];
#pragma unroll
    for (int i = 0; i < 15; ++i) {
        float v = l1[i];
        float sq = (v * v) * C;
        lx[i]      = fminf(fmaxf(sq, 0.0f), 1.0f);
        lx[15 + i] = fminf(fmaxf(v, 0.0f), 1.0f);
    }
    lx[30] = 0.0f;
    lx[31] = 0.0f;

    // ---- layers 2 + 3 fused ----
    float l3 = 0.0f;
#pragma unroll 4
    for (int j = 0; j < L3N; ++j) {
        float s = b2s[j];
        const float4* wr = (const float4*)(w2s + j * 32);
#pragma unroll
        for (int p = 0; p < 8; ++p) {
            float4 wv = wr[p];
            s = fmaf(lx[4 * p + 0], wv.x, s);
            s = fmaf(lx[4 * p + 1], wv.y, s);
            s = fmaf(lx[4 * p + 2], wv.z, s);
            s = fmaf(lx[4 * p + 3], wv.w, s);
        }
        float s2 = fminf(fmaxf(s, 0.0f), 1.0f);
        l3 = fmaf(s2, wos[j], l3);
    }

    float res = l3 + bo[b] + l1[15];
    if (valid) out[my_sidx] = res;
}

// ---------------- launch ----------------
extern "C" void kernel_launch(void* const* d_in, const int* in_sizes, int n_in,
                              void* d_out, int out_size) {
    const float* x  = (const float*)d_in[0];
    const int*   ls = (const int*)d_in[1];
    const float* W1 = (const float*)d_in[2];
    const float* b1 = (const float*)d_in[3];
    const float* Wf = (const float*)d_in[4];
    const float* bf = (const float*)d_in[5];
    const float* W2 = (const float*)d_in[6];
    const float* b2 = (const float*)d_in[7];
    const float* Wo = (const float*)d_in[8];
    const float* bo = (const float*)d_in[9];
    float* out = (float*)d_out;
    int n = in_sizes[1];
    if (n > BMAX) n = BMAX;

    cudaFuncSetAttribute(k_main, cudaFuncAttributeMaxDynamicSharedMemorySize, SMEM_BYTES);

    int hb = (n + 255) / 256;   // <= HB for n <= 16384
    k_prep<<<192, 256>>>(W1, b1, Wf, bf, W2);
    k_hist<<<hb, 256>>>(ls, n);
    k_scan<<<1, 256>>>();
    k_scatter<<<hb, 256>>>(ls, n);

    int nblk = (n + CTA_SAMPLES - 1) / CTA_SAMPLES + COUNT;
    k_main<<<nblk, 128, SMEM_BYTES>>>(x, b2, Wo, bo, out);
}

// round 3
// speedup vs baseline: 1.6615x; 1.6615x over previous
#include <cuda_runtime.h>
#include <cuda_bf16.h>

#define L1N 16
#define DIN 1536
#define COUNT 8
#define L3N 64
#define BMAX 16384
#define CTA_SAMPLES 128
#define THREADS 512
#define CK2 64                  // k per chunk
#define NCH2 (DIN / CK2)        // 24
#define XST2 68                 // x smem row stride
#define HB 64                   // max histogram blocks

// ---- device scratch ----
__device__ float g_wsum[COUNT * DIN * L1N];   // [b][k][16]
__device__ float g_bsum[COUNT * L1N];
__device__ float g_w2p[COUNT * L3N * 32];
__device__ int   g_bh[HB * COUNT];
__device__ int   g_aoff[COUNT + 1];
__device__ int   g_order[BMAX + COUNT * CTA_SAMPLES];

// ---------------- prep: fold W1+Wf, pad W2, per-block histogram ----------------
__global__ void k_prep(const float* __restrict__ W1, const float* __restrict__ b1,
                       const float* __restrict__ Wf, const float* __restrict__ bf,
                       const float* __restrict__ W2, const int* __restrict__ ls,
                       int n, int hb) {
    int tid = blockIdx.x * blockDim.x + threadIdx.x;
    int stride = gridDim.x * blockDim.x;
    for (int idx = tid; idx < COUNT * DIN * L1N; idx += stride) {
        int b = idx / (DIN * L1N);
        int r = idx - b * (DIN * L1N);
        int k = r >> 4;
        int o = r & 15;
        g_wsum[idx] = W1[(b * L1N + o) * DIN + k] + Wf[o * DIN + k];
    }
    for (int idx = tid; idx < COUNT * L3N * 32; idx += stride) {
        int b = idx >> 11;
        int j = (idx >> 5) & 63;
        int i = idx & 31;
        g_w2p[idx] = (i < 30) ? W2[(b * L3N + j) * 30 + i] : 0.0f;
    }
    for (int idx = tid; idx < COUNT * L1N; idx += stride) {
        int b = idx >> 4, o = idx & 15;
        g_bsum[idx] = b1[b * L1N + o] + bf[o];
    }
    // per-block histogram (blocks < hb)
    if ((int)blockIdx.x < hb) {
        __shared__ int sh[COUNT];
        int t = threadIdx.x;
        if (t < COUNT) sh[t] = 0;
        __syncthreads();
        int i = blockIdx.x * 256 + t;
        if (i < n) {
            int b = ls[i];
            unsigned act = __activemask();
            unsigned m = __match_any_sync(act, b);
            int lane = t & 31;
            int leader = __ffs(m) - 1;
            if (lane == leader) atomicAdd(&sh[b], __popc(m));
        }
        __syncthreads();
        if (t < COUNT) g_bh[blockIdx.x * COUNT + t] = sh[t];
    }
}

// ---------------- scatter with inline scan; block 0 also writes aoff + sentinels ----------------
__global__ void k_scatter(const int* __restrict__ ls, int n, int hb) {
    __shared__ int sh[HB * COUNT];
    __shared__ int s_aoff[COUNT + 1];
    __shared__ int s_cnt[COUNT];
    __shared__ int cur[COUNT];
    int t = threadIdx.x;
    for (int i = t; i < hb * COUNT; i += 256) sh[i] = g_bh[i];
    __syncthreads();
    if (t < COUNT) {
        int tot = 0;
        for (int j = 0; j < hb; ++j) tot += sh[j * COUNT + t];
        s_cnt[t] = tot;
    }
    __syncthreads();
    if (t == 0) {
        int off = 0;
        for (int b = 0; b < COUNT; ++b) {
            s_aoff[b] = off;
            off += (s_cnt[b] + CTA_SAMPLES - 1) & ~(CTA_SAMPLES - 1);
        }
        s_aoff[COUNT] = off;
        if (blockIdx.x == 0)
            for (int b = 0; b <= COUNT; ++b) g_aoff[b] = s_aoff[b];
    }
    __syncthreads();
    if (t < COUNT) {
        int run = s_aoff[t];
        for (int j = 0; j < (int)blockIdx.x; ++j) run += sh[j * COUNT + t];
        cur[t] = run;
    }
    __syncthreads();
    if (blockIdx.x == 0) {
        for (int b = 0; b < COUNT; ++b) {
            int s = s_aoff[b] + s_cnt[b];
            int e = s_aoff[b + 1];
            for (int i = s + t; i < e; i += 256) g_order[i] = -1;
        }
    }
    int i = blockIdx.x * 256 + t;
    if (i < n) {
        int b = ls[i];
        unsigned act = __activemask();
        unsigned m = __match_any_sync(act, b);
        int lane = t & 31;
        int leader = __ffs(m) - 1;
        int rank = __popc(m & ((1u << lane) - 1u));
        int base = 0;
        if (lane == leader) base = atomicAdd(&cur[b], __popc(m));
        base = __shfl_sync(act, base, leader);
        g_order[base + rank] = i;
    }
}

// ---------------- main fused kernel: 512 threads, 128 samples, 4-way k-slice ----------------
// smem floats: ws 24576 + w2s 2048 + bs 16 + b2 64 + wo 64 + xs 2*128*68 + sidx 128
#define SMEM_WORDS (24576 + 2048 + 16 + 64 + 64 + 2 * 128 * XST2 + 128)
#define SMEM_BYTES (SMEM_WORDS * 4)

__global__ void __launch_bounds__(THREADS, 1) k_main(const float* __restrict__ x,
                                                     const float* __restrict__ b2,
                                                     const float* __restrict__ Wo,
                                                     const float* __restrict__ bo,
                                                     float* __restrict__ out) {
    extern __shared__ float sm[];
    float* ws   = sm;                  // [k][16]
    float* w2s  = ws + 24576;          // [j][32]
    float* bs   = w2s + 2048;          // 16
    float* b2s  = bs + 16;             // 64
    float* wos  = b2s + 64;            // 64
    float* xs0  = wos + 64;            // 128*68
    float* xs1  = xs0 + 128 * XST2;    // 128*68
    int* sidx_s = (int*)(xs1 + 128 * XST2);  // 128

    int tid = threadIdx.x;
    int base = blockIdx.x * CTA_SAMPLES;
    if (base >= g_aoff[COUNT]) return;

    int b = 0;
#pragma unroll
    for (int t = 1; t < COUNT; ++t)
        if (base >= g_aoff[t]) b = t;

    // ---- stage weights ----
    {
        const float4* src = (const float4*)(g_wsum + b * (DIN * L1N));
        float4* dst = (float4*)ws;
#pragma unroll
        for (int r = 0; r < 12; ++r) dst[tid + r * THREADS] = src[tid + r * THREADS];
    }
    {
        const float4* src = (const float4*)(g_w2p + b * (L3N * 32));
        ((float4*)w2s)[tid & 511] = src[tid & 511];
    }
    if (tid < 16) bs[tid] = g_bsum[b * L1N + tid];
    else if (tid >= 32 && tid < 96) b2s[tid - 32] = b2[b * L3N + (tid - 32)];
    else if (tid >= 96 && tid < 160) wos[tid - 96] = Wo[b * L3N + (tid - 96)];
    if (tid < 128) sidx_s[tid] = g_order[base + tid];
    __syncthreads();

    // ---- loader assignment (fixed across chunks) ----
    const float4* p4[4];
#pragma unroll
    for (int r = 0; r < 4; ++r) {
        int i = tid + THREADS * r;
        int s = i >> 4;
        int k4 = i & 15;
        int sv = sidx_s[s];
        int srow = (sv >= 0) ? sv : 0;
        p4[r] = (const float4*)(x + (size_t)srow * DIN) + k4;
    }

    // ---- slice assignment ----
    int wid = tid >> 5, lane = tid & 31;
    int sl = wid & 3;                 // k-slice 0..3
    int myS = (wid >> 2) * 32 + lane; // sample 0..127

    unsigned long long acc[8];
#pragma unroll
    for (int i = 0; i < 8; ++i) acc[i] = 0ULL;

    const ulonglong2* wp = (const ulonglong2*)ws;

    float4 pf[4];
#pragma unroll
    for (int r = 0; r < 4; ++r) pf[r] = p4[r][0];

#pragma unroll 1
    for (int c = 0; c < NCH2; ++c) {
        float* xb = (c & 1) ? xs1 : xs0;
#pragma unroll
        for (int r = 0; r < 4; ++r) {
            int i = tid + THREADS * r;
            int s = i >> 4, k4 = i & 15;
            *(float4*)(xb + s * XST2 + k4 * 4) = pf[r];
        }
        __syncthreads();
        if (c + 1 < NCH2) {
#pragma unroll
            for (int r = 0; r < 4; ++r) pf[r] = p4[r][(c + 1) * 16];
        }
        const float* xrow = xb + myS * XST2 + sl * 16;
        int kg0 = c * CK2 + sl * 16;
#pragma unroll
        for (int kq = 0; kq < 16; kq += 4) {
            float4 xv = *(const float4*)(xrow + kq);
#pragma unroll
            for (int t4 = 0; t4 < 4; ++t4) {
                float xval = (t4 == 0) ? xv.x : (t4 == 1) ? xv.y : (t4 == 2) ? xv.z : xv.w;
                unsigned long long xd;
                asm("mov.b64 %0, {%1, %1};" : "=l"(xd) : "f"(xval));
                const ulonglong2* wr = wp + (unsigned)(kg0 + kq + t4) * 4;
#pragma unroll
                for (int p = 0; p < 4; ++p) {
                    ulonglong2 wv = wr[p];
                    asm("fma.rn.f32x2 %0, %1, %2, %0;"
                        : "+l"(acc[2 * p]) : "l"(xd), "l"(wv.x));
                    asm("fma.rn.f32x2 %0, %1, %2, %0;"
                        : "+l"(acc[2 * p + 1]) : "l"(xd), "l"(wv.y));
                }
            }
        }
    }
    __syncthreads();

    // ---- cross-slice reduction via smem (stride 17, conflict-free) ----
    float* red = xs0;  // [sl*128 + s][17]
    {
        float* br = red + (sl * 128 + myS) * 17;
#pragma unroll
        for (int p = 0; p < 8; ++p) {
            float lo, hi;
            asm("mov.b64 {%0, %1}, %2;" : "=f"(lo), "=f"(hi) : "l"(acc[p]));
            br[2 * p]     = lo;
            br[2 * p + 1] = hi;
        }
    }
    __syncthreads();

    // ---- tail: 4 j-groups x 128 samples ----
    int s2 = tid & 127;
    int jg = tid >> 7;
    float l1[16];
#pragma unroll
    for (int o = 0; o < 16; ++o) {
        float v = bs[o];
#pragma unroll
        for (int q = 0; q < 4; ++q) v += red[(q * 128 + s2) * 17 + o];
        l1[o] = v;
    }

    const float C = 127.0f / 128.0f;
    float lx[32];
#pragma unroll
    for (int i = 0; i < 15; ++i) {
        float v = l1[i];
        float sq = (v * v) * C;
        lx[i]      = fminf(fmaxf(sq, 0.0f), 1.0f);
        lx[15 + i] = fminf(fmaxf(v, 0.0f), 1.0f);
    }
    lx[30] = 0.0f;
    lx[31] = 0.0f;

    float l3p = 0.0f;
#pragma unroll 2
    for (int jj = 0; jj < 16; ++jj) {
        int j = jg * 16 + jj;
        float ssum = b2s[j];
        const float4* wr2 = (const float4*)(w2s + j * 32);
#pragma unroll
        for (int p = 0; p < 8; ++p) {
            float4 wv = wr2[p];
            ssum = fmaf(lx[4 * p + 0], wv.x, ssum);
            ssum = fmaf(lx[4 * p + 1], wv.y, ssum);
            ssum = fmaf(lx[4 * p + 2], wv.z, ssum);
            ssum = fmaf(lx[4 * p + 3], wv.w, ssum);
        }
        float sc = fminf(fmaxf(ssum, 0.0f), 1.0f);
        l3p = fmaf(sc, wos[j], l3p);
    }
    float* red2 = xs1;
    red2[jg * 128 + s2] = l3p;
    __syncthreads();

    if (tid < 128) {
        int sv = sidx_s[tid];
        if (sv >= 0) {
            float l3 = red2[tid] + red2[128 + tid] + red2[256 + tid] + red2[384 + tid];
            out[sv] = l3 + bo[b] + l1[15];
        }
    }
}

// ---------------- launch ----------------
extern "C" void kernel_launch(void* const* d_in, const int* in_sizes, int n_in,
                              void* d_out, int out_size) {
    const float* x  = (const float*)d_in[0];
    const int*   ls = (const int*)d_in[1];
    const float* W1 = (const float*)d_in[2];
    const float* b1 = (const float*)d_in[3];
    const float* Wf = (const float*)d_in[4];
    const float* bf = (const float*)d_in[5];
    const float* W2 = (const float*)d_in[6];
    const float* b2 = (const float*)d_in[7];
    const float* Wo = (const float*)d_in[8];
    const float* bo = (const float*)d_in[9];
    float* out = (float*)d_out;
    int n = in_sizes[1];
    if (n > BMAX) n = BMAX;

    cudaFuncSetAttribute(k_main, cudaFuncAttributeMaxDynamicSharedMemorySize, SMEM_BYTES);

    int hb = (n + 255) / 256;   // <= HB for n <= 16384
    k_prep<<<192, 256>>>(W1, b1, Wf, bf, W2, ls, n, hb);
    k_scatter<<<hb, 256>>>(ls, n, hb);

    int nblk = (n + CTA_SAMPLES - 1) / CTA_SAMPLES + COUNT;
    k_main<<<nblk, THREADS, SMEM_BYTES>>>(x, b2, Wo, bo, out);
}